// round 6
// baseline (speedup 1.0000x reference)
#include <cuda_runtime.h>
#include <cstdint>
#include <math.h>

#define B_ 4
#define L_ 256
#define D_ 512
#define H_ 8
#define DK_ 64

// Scratch (allocation-free rule: __device__ globals)
__device__ float g_qh[B_*H_*L_*DK_];
__device__ float g_kh[B_*H_*L_*DK_];
__device__ float g_vh[B_*H_*L_*DK_];
__device__ float g_ctx[B_*L_*D_];

__device__ __forceinline__ float tanh_fast(float x) {
    float y;
    asm("tanh.approx.f32 %0, %1;" : "=f"(y) : "f"(x));
    return y;
}

__device__ __forceinline__ float to_tf32f(float x) {
    uint32_t u;
    asm("cvt.rna.tf32.f32 %0, %1;" : "=r"(u) : "f"(x));
    return __uint_as_float(u);
}

// m16n8k8 tf32 MMA (sm_80+ PTX, works on plain compute_103 target)
__device__ __forceinline__ void mma_tf32(float* c, const uint32_t* a, const uint32_t* b) {
    asm volatile(
        "mma.sync.aligned.m16n8k8.row.col.f32.tf32.tf32.f32 "
        "{%0,%1,%2,%3}, {%4,%5,%6,%7}, {%8,%9}, {%0,%1,%2,%3};"
        : "+f"(c[0]), "+f"(c[1]), "+f"(c[2]), "+f"(c[3])
        : "r"(a[0]), "r"(a[1]), "r"(a[2]), "r"(a[3]),
          "r"(b[0]), "r"(b[1]));
}

// ===========================================================================
// 3xTF32 tensor-core GEMM, software-pipelined:
//   - register prefetch of stage s+1 LDG under stage-s MMAs
//   - double-buffered hi/lo SMEM, ONE __syncthreads per K-stage
// C[m0:m0+MT, n0:n0+64] = X @ W + bias  (X: [1024,512], W: [512,512] row-major)
// ===========================================================================
#define A_STRIDE 36
#define B_STRIDE 68

template<int MT, int WM, int WN, bool HEADSPLIT>
__device__ __forceinline__ void gemm3x_core(
    const float* __restrict__ X, const float* __restrict__ W,
    const float* __restrict__ bias, float* __restrict__ Y)
{
    extern __shared__ __align__(16) float smf[];
    constexpr int A_FLOATS = MT * A_STRIDE;
    constexpr int B_FLOATS = 32 * B_STRIDE;
    constexpr int BUF_FLOATS = 2 * A_FLOATS + 2 * B_FLOATS;

    constexpr int MTILES = (MT / WM) / 16;
    constexpr int NTILES = (64 / WN) / 8;
    constexpr int TPR = 256 / MT;      // threads per A row
    constexpr int KPT = 32 / TPR;      // k floats per thread (16 or 8)
    constexpr int APF = KPT / 4;       // float4 chunks of A per thread

    const int tid = threadIdx.x;
    const int wid = tid >> 5, lane = tid & 31;
    const int g = lane >> 2, t4 = lane & 3;
    const int warp_m = (wid % WM) * (MT / WM);
    const int warp_n = (wid / WM) * (64 / WN);
    const int m0 = blockIdx.x * MT;
    const int n0 = blockIdx.y * 64;

    const int am = tid / TPR;
    const int aks = (tid % TPR) * KPT;
    const int bk = tid >> 3;
    const int bn = (tid & 7) * 8;

    float acc[MTILES][NTILES][4];
    #pragma unroll
    for (int i = 0; i < MTILES; i++)
        #pragma unroll
        for (int j = 0; j < NTILES; j++)
            #pragma unroll
            for (int c = 0; c < 4; c++) acc[i][j][c] = 0.0f;

    const float* Abase = X + (size_t)(m0 + am) * D_ + aks;
    const float* Bbase = W + (size_t)bk * D_ + n0 + bn;

    float4 aP[APF], bP[2];

    // ---- prologue: LDG stage 0 into registers ----
    #pragma unroll
    for (int u = 0; u < APF; u++) aP[u] = *(const float4*)(Abase + u * 4);
    bP[0] = *(const float4*)(Bbase);
    bP[1] = *(const float4*)(Bbase + 4);

    for (int s = 0; s < 16; s++) {
        const int buf = s & 1;
        float* As_hi = smf + buf * BUF_FLOATS;
        float* As_lo = As_hi + A_FLOATS;
        float* Bs_hi = As_lo + A_FLOATS;
        float* Bs_lo = Bs_hi + B_FLOATS;

        // ---- STS: convert register-staged tiles to hi/lo in smem[buf] ----
        #pragma unroll
        for (int u = 0; u < APF; u++) {
            float4 xv = aP[u];
            float4 hi, lo;
            hi.x = to_tf32f(xv.x); lo.x = to_tf32f(xv.x - hi.x);
            hi.y = to_tf32f(xv.y); lo.y = to_tf32f(xv.y - hi.y);
            hi.z = to_tf32f(xv.z); lo.z = to_tf32f(xv.z - hi.z);
            hi.w = to_tf32f(xv.w); lo.w = to_tf32f(xv.w - hi.w);
            *(float4*)&As_hi[am * A_STRIDE + aks + u * 4] = hi;
            *(float4*)&As_lo[am * A_STRIDE + aks + u * 4] = lo;
        }
        #pragma unroll
        for (int u = 0; u < 2; u++) {
            float4 wv = bP[u];
            float4 hi, lo;
            hi.x = to_tf32f(wv.x); lo.x = to_tf32f(wv.x - hi.x);
            hi.y = to_tf32f(wv.y); lo.y = to_tf32f(wv.y - hi.y);
            hi.z = to_tf32f(wv.z); lo.z = to_tf32f(wv.z - hi.z);
            hi.w = to_tf32f(wv.w); lo.w = to_tf32f(wv.w - hi.w);
            *(float4*)&Bs_hi[bk * B_STRIDE + bn + u * 4] = hi;
            *(float4*)&Bs_lo[bk * B_STRIDE + bn + u * 4] = lo;
        }
        __syncthreads();

        // ---- prefetch stage s+1 (latency hidden under MMAs below) ----
        if (s < 15) {
            const float* an = Abase + (s + 1) * 32;
            const float* bnx = Bbase + (size_t)(s + 1) * 32 * D_;
            #pragma unroll
            for (int u = 0; u < APF; u++) aP[u] = *(const float4*)(an + u * 4);
            bP[0] = *(const float4*)(bnx);
            bP[1] = *(const float4*)(bnx + 4);
        }

        // ---- MMA over smem[buf] ----
        #pragma unroll
        for (int kk = 0; kk < 4; kk++) {
            const int kb = kk * 8;
            uint32_t ahi[MTILES][4], alo[MTILES][4];
            #pragma unroll
            for (int i = 0; i < MTILES; i++) {
                int rm = warp_m + i * 16;
                ahi[i][0] = __float_as_uint(As_hi[(rm + g)     * A_STRIDE + kb + t4]);
                ahi[i][1] = __float_as_uint(As_hi[(rm + 8 + g) * A_STRIDE + kb + t4]);
                ahi[i][2] = __float_as_uint(As_hi[(rm + g)     * A_STRIDE + kb + t4 + 4]);
                ahi[i][3] = __float_as_uint(As_hi[(rm + 8 + g) * A_STRIDE + kb + t4 + 4]);
                alo[i][0] = __float_as_uint(As_lo[(rm + g)     * A_STRIDE + kb + t4]);
                alo[i][1] = __float_as_uint(As_lo[(rm + 8 + g) * A_STRIDE + kb + t4]);
                alo[i][2] = __float_as_uint(As_lo[(rm + g)     * A_STRIDE + kb + t4 + 4]);
                alo[i][3] = __float_as_uint(As_lo[(rm + 8 + g) * A_STRIDE + kb + t4 + 4]);
            }
            uint32_t bhi[NTILES][2], blo[NTILES][2];
            #pragma unroll
            for (int j = 0; j < NTILES; j++) {
                int cn = warp_n + j * 8 + g;
                bhi[j][0] = __float_as_uint(Bs_hi[(kb + t4)     * B_STRIDE + cn]);
                bhi[j][1] = __float_as_uint(Bs_hi[(kb + t4 + 4) * B_STRIDE + cn]);
                blo[j][0] = __float_as_uint(Bs_lo[(kb + t4)     * B_STRIDE + cn]);
                blo[j][1] = __float_as_uint(Bs_lo[(kb + t4 + 4) * B_STRIDE + cn]);
            }
            #pragma unroll
            for (int i = 0; i < MTILES; i++)
                #pragma unroll
                for (int j = 0; j < NTILES; j++) {
                    mma_tf32(acc[i][j], ahi[i], bhi[j]);
                    mma_tf32(acc[i][j], ahi[i], blo[j]);
                    mma_tf32(acc[i][j], alo[i], bhi[j]);
                }
        }
    }

    // ---- Epilogue: bias + store (c0,c1 -> row g; c2,c3 -> row g+8) ----
    #pragma unroll
    for (int i = 0; i < MTILES; i++) {
        #pragma unroll
        for (int j = 0; j < NTILES; j++) {
            int col_loc = warp_n + j * 8 + 2 * t4;
            int cng = n0 + col_loc;
            float b0 = bias[cng], b1 = bias[cng + 1];
            int r0 = m0 + warp_m + i * 16 + g;
            int r1 = r0 + 8;
            float2 v0 = make_float2(acc[i][j][0] + b0, acc[i][j][1] + b1);
            float2 v1 = make_float2(acc[i][j][2] + b0, acc[i][j][3] + b1);
            if (HEADSPLIT) {
                int h = blockIdx.y;
                float* d0 = Y + ((size_t)((r0 >> 8) * H_ + h) * L_ + (r0 & 255)) * DK_ + col_loc;
                float* d1 = Y + ((size_t)((r1 >> 8) * H_ + h) * L_ + (r1 & 255)) * DK_ + col_loc;
                *(float2*)d0 = v0;
                *(float2*)d1 = v1;
            } else {
                *(float2*)(Y + (size_t)r0 * D_ + cng) = v0;
                *(float2*)(Y + (size_t)r1 * D_ + cng) = v1;
            }
        }
    }
}

constexpr int gemm_smem_bytes(int mt) {
    return 2 * (2 * mt * A_STRIDE + 2 * 32 * B_STRIDE) * 4;
}

// QKV: grid (8, 8, 3), MT=128, warps 4x2, head-split output
__global__ __launch_bounds__(256) void qkv_mma_kernel(
    const float* __restrict__ q, const float* __restrict__ k, const float* __restrict__ v,
    const float* __restrict__ Wq, const float* __restrict__ bq,
    const float* __restrict__ Wk, const float* __restrict__ bk,
    const float* __restrict__ Wv, const float* __restrict__ bv)
{
    int z = blockIdx.z;
    const float* X    = (z == 0) ? q  : (z == 1 ? k  : v);
    const float* W    = (z == 0) ? Wq : (z == 1 ? Wk : Wv);
    const float* bias = (z == 0) ? bq : (z == 1 ? bk : bv);
    float* out        = (z == 0) ? g_qh : (z == 1 ? g_kh : g_vh);
    gemm3x_core<128, 4, 2, true>(X, W, bias, out);
}

// Output projection: grid (16, 8), MT=64, warps 2x4, flat output
__global__ __launch_bounds__(256) void out_mma_kernel(
    const float* __restrict__ W, const float* __restrict__ bias, float* __restrict__ Y)
{
    gemm3x_core<64, 2, 4, false>(g_ctx, W, bias, Y);
}

// ===========================================================================
// Fused Bahdanau attention (unchanged). One CTA per (b,h,64-row block).
// ===========================================================================
#define ATTN_SMEM_FLOATS (64*68 + 64*68 + 256*64 + 64*260 + 64 + 64)
#define ATTN_SMEM_BYTES  (ATTN_SMEM_FLOATS * 4)

__global__ __launch_bounds__(256) void attn_kernel(
    const int* __restrict__ mask, const float* __restrict__ vp)
{
    extern __shared__ __align__(16) float sm[];
    float* Qs   = sm;
    float* Ks   = Qs + 64 * 68;
    float* Vs   = Ks + 64 * 68;
    float* S    = Vs + 256 * 64;
    float* vps  = S + 64 * 260;
    float* rinv = vps + 64;

    int tid = threadIdx.x;
    int bh = blockIdx.y;
    int b = bh >> 3;
    int h = bh & 7;
    int i0 = blockIdx.x * 64;

    const float* qh  = g_qh + (size_t)(bh * L_ + i0) * DK_;
    const float* khp = g_kh + (size_t)bh * L_ * DK_;
    const float* vhp = g_vh + (size_t)bh * L_ * DK_;

    if (tid < 64) vps[tid] = vp[h * DK_ + tid];

    {
        int i  = tid >> 2;
        int d0 = (tid & 3) * 16;
        #pragma unroll
        for (int u = 0; u < 4; u++) {
            float4 t4 = *(const float4*)&qh[(size_t)i * DK_ + d0 + u * 4];
            Qs[(d0 + u * 4 + 0) * 68 + i] = t4.x;
            Qs[(d0 + u * 4 + 1) * 68 + i] = t4.y;
            Qs[(d0 + u * 4 + 2) * 68 + i] = t4.z;
            Qs[(d0 + u * 4 + 3) * 68 + i] = t4.w;
        }
    }
    {
        const float4* src = (const float4*)vhp;
        float4* dst = (float4*)Vs;
        #pragma unroll
        for (int t = tid; t < (L_ * DK_) / 4; t += 256) dst[t] = src[t];
    }

    int ti = tid & 15;
    int tj = tid >> 4;

    for (int jb = 0; jb < 4; jb++) {
        __syncthreads();
        {
            int j  = tid >> 2;
            int d0 = (tid & 3) * 16;
            const float* kr = khp + (size_t)(jb * 64 + j) * DK_;
            #pragma unroll
            for (int u = 0; u < 4; u++) {
                float4 t4 = *(const float4*)&kr[d0 + u * 4];
                Ks[(d0 + u * 4 + 0) * 68 + j] = t4.x;
                Ks[(d0 + u * 4 + 1) * 68 + j] = t4.y;
                Ks[(d0 + u * 4 + 2) * 68 + j] = t4.z;
                Ks[(d0 + u * 4 + 3) * 68 + j] = t4.w;
            }
        }
        __syncthreads();

        float acc[4][4] = {};
        #pragma unroll 2
        for (int d = 0; d < 64; d++) {
            float w = vps[d];
            float4 qv = *(const float4*)&Qs[d * 68 + ti * 4];
            float4 kv = *(const float4*)&Ks[d * 68 + tj * 4];
            float qa[4] = {qv.x, qv.y, qv.z, qv.w};
            float kb[4] = {kv.x, kv.y, kv.z, kv.w};
            #pragma unroll
            for (int a = 0; a < 4; a++)
                #pragma unroll
                for (int c = 0; c < 4; c++)
                    acc[a][c] += w * tanh_fast(qa[a] + kb[c]);
        }
        #pragma unroll
        for (int a = 0; a < 4; a++)
            #pragma unroll
            for (int c = 0; c < 4; c++)
                S[(ti * 4 + a) * 260 + jb * 64 + tj * 4 + c] = acc[a][c];
    }
    __syncthreads();

    {
        int warp = tid >> 5, lane = tid & 31;
        for (int r = 0; r < 8; r++) {
            int row = warp * 8 + r;
            const int* mrow = mask + ((size_t)b * L_ + i0 + row) * L_;
            float vals[8];
            float mmax = -3.4e38f;
            #pragma unroll
            for (int c8 = 0; c8 < 8; c8++) {
                int c = c8 * 32 + lane;
                float s = S[row * 260 + c];
                if (mrow[c] == 0) s = -1.0e9f;
                vals[c8] = s;
                mmax = fmaxf(mmax, s);
            }
            #pragma unroll
            for (int off = 16; off > 0; off >>= 1)
                mmax = fmaxf(mmax, __shfl_xor_sync(0xFFFFFFFFu, mmax, off));
            float sum = 0.0f;
            #pragma unroll
            for (int c8 = 0; c8 < 8; c8++) {
                float e = __expf(vals[c8] - mmax);
                S[row * 260 + c8 * 32 + lane] = e;
                sum += e;
            }
            #pragma unroll
            for (int off = 16; off > 0; off >>= 1)
                sum += __shfl_xor_sync(0xFFFFFFFFu, sum, off);
            if (lane == 0) rinv[row] = 1.0f / sum;
        }
    }
    __syncthreads();

    {
        int i   = tid >> 2;
        int dk0 = (tid & 3) * 16;
        float o[16] = {};
        #pragma unroll 4
        for (int j = 0; j < L_; j++) {
            float p = S[i * 260 + j];
            const float4* vr = (const float4*)&Vs[j * DK_ + dk0];
            float4 v0 = vr[0], v1 = vr[1], v2 = vr[2], v3 = vr[3];
            o[0]  += p * v0.x; o[1]  += p * v0.y; o[2]  += p * v0.z; o[3]  += p * v0.w;
            o[4]  += p * v1.x; o[5]  += p * v1.y; o[6]  += p * v1.z; o[7]  += p * v1.w;
            o[8]  += p * v2.x; o[9]  += p * v2.y; o[10] += p * v2.z; o[11] += p * v2.w;
            o[12] += p * v3.x; o[13] += p * v3.y; o[14] += p * v3.z; o[15] += p * v3.w;
        }
        float inv = rinv[i];
        float* dst = &g_ctx[((size_t)b * L_ + i0 + i) * D_ + h * DK_ + dk0];
        #pragma unroll
        for (int u = 0; u < 4; u++) {
            float4 r;
            r.x = o[u * 4 + 0] * inv;
            r.y = o[u * 4 + 1] * inv;
            r.z = o[u * 4 + 2] * inv;
            r.w = o[u * 4 + 3] * inv;
            *(float4*)&dst[u * 4] = r;
        }
    }
}

// ===========================================================================
extern "C" void kernel_launch(void* const* d_in, const int* in_sizes, int n_in,
                              void* d_out, int out_size)
{
    const float* q    = (const float*)d_in[0];
    const float* k    = (const float*)d_in[1];
    const float* v    = (const float*)d_in[2];
    const int*   mask = (const int*)  d_in[3];
    const float* Wq   = (const float*)d_in[4];
    const float* bq   = (const float*)d_in[5];
    const float* Wk   = (const float*)d_in[6];
    const float* bk   = (const float*)d_in[7];
    const float* Wv   = (const float*)d_in[8];
    const float* bv   = (const float*)d_in[9];
    const float* vp   = (const float*)d_in[10];
    const float* W0   = (const float*)d_in[11];
    const float* b0   = (const float*)d_in[12];
    float* out = (float*)d_out;

    static bool attr_set = false;
    if (!attr_set) {
        cudaFuncSetAttribute(attn_kernel,
                             cudaFuncAttributeMaxDynamicSharedMemorySize, ATTN_SMEM_BYTES);
        cudaFuncSetAttribute(qkv_mma_kernel,
                             cudaFuncAttributeMaxDynamicSharedMemorySize, gemm_smem_bytes(128));
        cudaFuncSetAttribute(out_mma_kernel,
                             cudaFuncAttributeMaxDynamicSharedMemorySize, gemm_smem_bytes(64));
        attr_set = true;
    }

    qkv_mma_kernel<<<dim3(8, 8, 3), 256, gemm_smem_bytes(128)>>>(
        q, k, v, Wq, bq, Wk, bk, Wv, bv);
    attn_kernel<<<dim3(4, 32), 256, ATTN_SMEM_BYTES>>>(mask, vp);
    out_mma_kernel<<<dim3(16, 8), 256, gemm_smem_bytes(64)>>>(W0, b0, out);
}

// round 7
// speedup vs baseline: 1.1552x; 1.1552x over previous
#include <cuda_runtime.h>
#include <cuda_bf16.h>
#include <cstdint>
#include <math.h>

#define B_ 4
#define L_ 256
#define D_ 512
#define H_ 8
#define DK_ 64

typedef __nv_bfloat16 bf16;
typedef __nv_bfloat162 bf162;

// ---------------------------------------------------------------------------
// Scratch (allocation-free rule: __device__ globals)
// ---------------------------------------------------------------------------
__device__ float g_qh[B_*H_*L_*DK_];
__device__ float g_kh[B_*H_*L_*DK_];
__device__ float g_vh[B_*H_*L_*DK_];

__device__ __align__(16) bf16 g_Xhi[3*1024*512];   // q,k,v inputs [m][k]
__device__ __align__(16) bf16 g_Xlo[3*1024*512];
__device__ __align__(16) bf16 g_Whi[4*512*512];    // Wq,Wk,Wv,W0 TRANSPOSED [n][k]
__device__ __align__(16) bf16 g_Wlo[4*512*512];
__device__ __align__(16) bf16 g_ctx_hi[1024*512];  // attention context [m][k]
__device__ __align__(16) bf16 g_ctx_lo[1024*512];

// ---------------------------------------------------------------------------
__device__ __forceinline__ uint32_t smem_u32(const void* p) {
    uint32_t a;
    asm("{ .reg .u64 t; cvta.to.shared.u64 t, %1; cvt.u32.u64 %0, t; }" : "=r"(a) : "l"(p));
    return a;
}
__device__ __forceinline__ float tanh_fast(float x) {
    float y;
    asm("tanh.approx.f32 %0, %1;" : "=f"(y) : "f"(x));
    return y;
}
__device__ __forceinline__ void ldm_x4(uint32_t* r, uint32_t addr) {
    asm volatile("ldmatrix.sync.aligned.m8n8.x4.shared.b16 {%0,%1,%2,%3}, [%4];"
        : "=r"(r[0]), "=r"(r[1]), "=r"(r[2]), "=r"(r[3]) : "r"(addr));
}
__device__ __forceinline__ void mma_bf16(float* c, const uint32_t* a, const uint32_t* b) {
    asm volatile(
        "mma.sync.aligned.m16n8k16.row.col.f32.bf16.bf16.f32 "
        "{%0,%1,%2,%3}, {%4,%5,%6,%7}, {%8,%9}, {%0,%1,%2,%3};"
        : "+f"(c[0]), "+f"(c[1]), "+f"(c[2]), "+f"(c[3])
        : "r"(a[0]), "r"(a[1]), "r"(a[2]), "r"(a[3]), "r"(b[0]), "r"(b[1]));
}
__device__ __forceinline__ void split_bf(float x, bf16& hi, bf16& lo) {
    hi = __float2bfloat16_rn(x);
    lo = __float2bfloat16_rn(x - __bfloat162float(hi));
}

// ---------------------------------------------------------------------------
// One-time fp32 -> (hi,lo) bf16 converts
// ---------------------------------------------------------------------------
__global__ __launch_bounds__(256) void convert_x_kernel(
    const float* __restrict__ q, const float* __restrict__ k, const float* __restrict__ v)
{
    int z = blockIdx.y;
    const float* src = (z == 0) ? q : (z == 1 ? k : v);
    int i = (blockIdx.x * 256 + threadIdx.x) * 4;
    float4 x = *(const float4*)(src + i);
    bf16 h0, l0, h1, l1, h2, l2, h3, l3;
    split_bf(x.x, h0, l0); split_bf(x.y, h1, l1);
    split_bf(x.z, h2, l2); split_bf(x.w, h3, l3);
    size_t base = (size_t)z * (1024*512) + i;
    bf162* ph = (bf162*)&g_Xhi[base];
    bf162* pl = (bf162*)&g_Xlo[base];
    ph[0] = bf162(h0, h1); ph[1] = bf162(h2, h3);
    pl[0] = bf162(l0, l1); pl[1] = bf162(l2, l3);
}

// W [k][n] -> [n][k] transpose + hi/lo split.  block (32,8), grid (16,16,4)
__global__ __launch_bounds__(256) void convert_w_kernel(
    const float* __restrict__ Wq, const float* __restrict__ Wk,
    const float* __restrict__ Wv, const float* __restrict__ W0)
{
    __shared__ float tile[32][33];
    int z = blockIdx.z;
    const float* W = (z == 0) ? Wq : (z == 1 ? Wk : (z == 2 ? Wv : W0));
    int k0 = blockIdx.x * 32, n0 = blockIdx.y * 32;
    int tx = threadIdx.x, ty = threadIdx.y;
    #pragma unroll
    for (int it = 0; it < 4; it++)
        tile[ty + it * 8][tx] = W[(size_t)(k0 + ty + it * 8) * D_ + n0 + tx];
    __syncthreads();
    size_t zb = (size_t)z * (512*512);
    #pragma unroll
    for (int it = 0; it < 4; it++) {
        int nr = ty + it * 8;
        bf16 hi, lo;
        split_bf(tile[tx][nr], hi, lo);
        g_Whi[zb + (size_t)(n0 + nr) * D_ + k0 + tx] = hi;
        g_Wlo[zb + (size_t)(n0 + nr) * D_ + k0 + tx] = lo;
    }
}

// ---------------------------------------------------------------------------
// 3xBF16 tensor-core GEMM: C[m0:+128, n0:+64] = A @ B^T + bias
// A [1024][512] hi/lo bf16 row-major; B [n=512][k=512] hi/lo bf16 (transposed W).
// K-stage 32, double-buffered, 1 sync/stage, ldmatrix fragments.
// 8 warps: 4(M) x 2(N); warp tile 32(m) x 32(n).
// ---------------------------------------------------------------------------
#define SA 40
#define A_HALVES (128*SA)
#define B_HALVES (64*SA)
#define GEMM_BUF_H (2*A_HALVES + 2*B_HALVES)
#define GEMM_SMEM_BYTES (2*GEMM_BUF_H*2)

template<bool HEADSPLIT>
__device__ __forceinline__ void gemm_core(
    const bf16* __restrict__ Ahi_g, const bf16* __restrict__ Alo_g,
    const bf16* __restrict__ Bhi_g, const bf16* __restrict__ Blo_g,
    const float* __restrict__ bias, float* __restrict__ Y)
{
    extern __shared__ __align__(16) bf16 smh[];
    const int tid = threadIdx.x;
    const int lane = tid & 31, wid = tid >> 5;
    const int g = lane >> 2, t4 = lane & 3;
    const int warp_m = (wid & 3) * 32;
    const int warp_n = (wid >> 2) * 32;
    const int m0 = blockIdx.x * 128, n0 = blockIdx.y * 64;

    const int am = tid >> 1, ah = (tid & 1) * 16;
    const int bn = tid >> 2, bh = (tid & 3) * 8;
    const bf16* Asrc_h = Ahi_g + (size_t)(m0 + am) * D_ + ah;
    const bf16* Asrc_l = Alo_g + (size_t)(m0 + am) * D_ + ah;
    const bf16* Bsrc_h = Bhi_g + (size_t)(n0 + bn) * D_ + bh;
    const bf16* Bsrc_l = Blo_g + (size_t)(n0 + bn) * D_ + bh;

    float acc[2][4][4];
    #pragma unroll
    for (int i = 0; i < 2; i++)
        #pragma unroll
        for (int j = 0; j < 4; j++)
            #pragma unroll
            for (int c = 0; c < 4; c++) acc[i][j][c] = 0.0f;

    // ldmatrix per-lane addresses
    const int lrow = lane & 15;         // A: row within 16-block
    const int lk   = (lane >> 4) * 8;   // A: k-half selector
    const int bln  = lane & 7;          // B rows
    const int bseg = (lane >> 3) & 1;   // B k-half
    const int bhi16 = (lane >> 4);      // B n 16-block
    const uint32_t smem_base = smem_u32(smh);
    const uint32_t aoff0 = ((warp_m + lrow)      * SA + lk) * 2;
    const uint32_t aoff1 = ((warp_m + 16 + lrow) * SA + lk) * 2;
    const uint32_t boff0 = ((warp_n + bln)       * SA + bseg * 8) * 2 + bhi16 * (8 * SA * 2);
    const uint32_t boff1 = boff0 + 16 * SA * 2;

    uint4 rAh0, rAh1, rAl0, rAl1, rBh, rBl;
    rAh0 = *(const uint4*)(Asrc_h);  rAh1 = *(const uint4*)(Asrc_h + 8);
    rAl0 = *(const uint4*)(Asrc_l);  rAl1 = *(const uint4*)(Asrc_l + 8);
    rBh  = *(const uint4*)(Bsrc_h);  rBl  = *(const uint4*)(Bsrc_l);

    for (int s = 0; s < 16; s++) {
        const int buf = s & 1;
        bf16* Ah_s = smh + buf * GEMM_BUF_H;
        bf16* Al_s = Ah_s + A_HALVES;
        bf16* Bh_s = Al_s + A_HALVES;
        bf16* Bl_s = Bh_s + B_HALVES;

        *(uint4*)&Ah_s[am * SA + ah]     = rAh0;
        *(uint4*)&Ah_s[am * SA + ah + 8] = rAh1;
        *(uint4*)&Al_s[am * SA + ah]     = rAl0;
        *(uint4*)&Al_s[am * SA + ah + 8] = rAl1;
        *(uint4*)&Bh_s[bn * SA + bh] = rBh;
        *(uint4*)&Bl_s[bn * SA + bh] = rBl;
        __syncthreads();

        if (s < 15) {
            const int off = (s + 1) * 32;
            rAh0 = *(const uint4*)(Asrc_h + off); rAh1 = *(const uint4*)(Asrc_h + off + 8);
            rAl0 = *(const uint4*)(Asrc_l + off); rAl1 = *(const uint4*)(Asrc_l + off + 8);
            rBh  = *(const uint4*)(Bsrc_h + off); rBl  = *(const uint4*)(Bsrc_l + off);
        }

        const uint32_t base = smem_base + (uint32_t)(buf * GEMM_BUF_H * 2);
        const uint32_t aBh = base;
        const uint32_t aBl = base + A_HALVES * 2;
        const uint32_t bBh = base + 2 * A_HALVES * 2;
        const uint32_t bBl = bBh + B_HALVES * 2;

        #pragma unroll
        for (int kk = 0; kk < 2; kk++) {
            const uint32_t ko = kk * 32;   // 16 halves
            uint32_t Ah0[4], Ah1[4], Al0[4], Al1[4];
            uint32_t Bh0[4], Bh1[4], Bl0[4], Bl1[4];
            ldm_x4(Ah0, aBh + aoff0 + ko);
            ldm_x4(Ah1, aBh + aoff1 + ko);
            ldm_x4(Al0, aBl + aoff0 + ko);
            ldm_x4(Al1, aBl + aoff1 + ko);
            ldm_x4(Bh0, bBh + boff0 + ko);
            ldm_x4(Bh1, bBh + boff1 + ko);
            ldm_x4(Bl0, bBl + boff0 + ko);
            ldm_x4(Bl1, bBl + boff1 + ko);

            #pragma unroll
            for (int i = 0; i < 2; i++) {
                uint32_t* ahp = i ? Ah1 : Ah0;
                uint32_t* alp = i ? Al1 : Al0;
                #pragma unroll
                for (int j = 0; j < 4; j++) {
                    uint32_t* bhp = (j < 2) ? Bh0 : Bh1;
                    uint32_t* blp = (j < 2) ? Bl0 : Bl1;
                    uint32_t bhf[2] = { bhp[(j & 1) * 2], bhp[(j & 1) * 2 + 1] };
                    uint32_t blf[2] = { blp[(j & 1) * 2], blp[(j & 1) * 2 + 1] };
                    mma_bf16(acc[i][j], ahp, bhf);
                    mma_bf16(acc[i][j], ahp, blf);
                    mma_bf16(acc[i][j], alp, bhf);
                }
            }
        }
    }

    #pragma unroll
    for (int i = 0; i < 2; i++) {
        #pragma unroll
        for (int j = 0; j < 4; j++) {
            int col_loc = warp_n + (j >> 1) * 16 + (j & 1) * 8 + 2 * t4;
            int cng = n0 + col_loc;
            float b0 = bias[cng], b1 = bias[cng + 1];
            int r0 = m0 + warp_m + i * 16 + g;
            int r1 = r0 + 8;
            float2 v0 = make_float2(acc[i][j][0] + b0, acc[i][j][1] + b1);
            float2 v1 = make_float2(acc[i][j][2] + b0, acc[i][j][3] + b1);
            if (HEADSPLIT) {
                int h = blockIdx.y;
                float* d0 = Y + ((size_t)((r0 >> 8) * H_ + h) * L_ + (r0 & 255)) * DK_ + col_loc;
                float* d1 = Y + ((size_t)((r1 >> 8) * H_ + h) * L_ + (r1 & 255)) * DK_ + col_loc;
                *(float2*)d0 = v0;
                *(float2*)d1 = v1;
            } else {
                *(float2*)(Y + (size_t)r0 * D_ + cng) = v0;
                *(float2*)(Y + (size_t)r1 * D_ + cng) = v1;
            }
        }
    }
}

__global__ __launch_bounds__(256, 2) void qkv_mma_kernel(
    const float* __restrict__ bq, const float* __restrict__ bk, const float* __restrict__ bv)
{
    int z = blockIdx.z;
    const float* bias = (z == 0) ? bq : (z == 1 ? bk : bv);
    float* out = (z == 0) ? g_qh : (z == 1 ? g_kh : g_vh);
    gemm_core<true>(g_Xhi + (size_t)z * (1024*512), g_Xlo + (size_t)z * (1024*512),
                    g_Whi + (size_t)z * (512*512),  g_Wlo + (size_t)z * (512*512),
                    bias, out);
}

__global__ __launch_bounds__(256, 2) void out_mma_kernel(
    const float* __restrict__ b0, float* __restrict__ Y)
{
    gemm_core<false>(g_ctx_hi, g_ctx_lo,
                     g_Whi + (size_t)3 * (512*512), g_Wlo + (size_t)3 * (512*512),
                     b0, Y);
}

// ---------------------------------------------------------------------------
// Fused Bahdanau attention, 512 threads. One CTA per (b,h,64-row i-block).
// ---------------------------------------------------------------------------
#define ATTN_SMEM_FLOATS (64*68 + 64*68 + 256*64 + 64*260 + 64 + 64)
#define ATTN_SMEM_BYTES  (ATTN_SMEM_FLOATS * 4)

__global__ __launch_bounds__(512) void attn_kernel(
    const int* __restrict__ mask, const float* __restrict__ vp)
{
    extern __shared__ __align__(16) float sm[];
    float* Qs   = sm;                  // [d][i] 64x68
    float* Ks   = Qs + 64 * 68;        // [d][j] 64x68
    float* Vs   = Ks + 64 * 68;        // [j][dk] 256x64
    float* S    = Vs + 256 * 64;       // [i][j] 64x260
    float* vps  = S + 64 * 260;
    float* rinv = vps + 64;

    int tid = threadIdx.x;
    int bh = blockIdx.y;
    int b = bh >> 3;
    int h = bh & 7;
    int i0 = blockIdx.x * 64;

    const float* qh  = g_qh + (size_t)(bh * L_ + i0) * DK_;
    const float* khp = g_kh + (size_t)bh * L_ * DK_;
    const float* vhp = g_vh + (size_t)bh * L_ * DK_;

    if (tid < 64) vps[tid] = vp[h * DK_ + tid];

    {
        int i = tid >> 3, d0 = (tid & 7) * 8;
        float4 t0 = *(const float4*)&qh[(size_t)i * DK_ + d0];
        float4 t1 = *(const float4*)&qh[(size_t)i * DK_ + d0 + 4];
        Qs[(d0 + 0) * 68 + i] = t0.x; Qs[(d0 + 1) * 68 + i] = t0.y;
        Qs[(d0 + 2) * 68 + i] = t0.z; Qs[(d0 + 3) * 68 + i] = t0.w;
        Qs[(d0 + 4) * 68 + i] = t1.x; Qs[(d0 + 5) * 68 + i] = t1.y;
        Qs[(d0 + 6) * 68 + i] = t1.z; Qs[(d0 + 7) * 68 + i] = t1.w;
    }
    {
        const float4* src = (const float4*)vhp;
        float4* dst = (float4*)Vs;
        #pragma unroll
        for (int t = tid; t < (L_ * DK_) / 4; t += 512) dst[t] = src[t];
    }

    const int ti = tid & 15;    // rows ti*4..+3
    const int tj = tid >> 4;    // cols tj*2..+1

    for (int jb = 0; jb < 4; jb++) {
        __syncthreads();
        {
            int j = tid >> 3, d0 = (tid & 7) * 8;
            const float* kr = khp + (size_t)(jb * 64 + j) * DK_;
            float4 t0 = *(const float4*)&kr[d0];
            float4 t1 = *(const float4*)&kr[d0 + 4];
            Ks[(d0 + 0) * 68 + j] = t0.x; Ks[(d0 + 1) * 68 + j] = t0.y;
            Ks[(d0 + 2) * 68 + j] = t0.z; Ks[(d0 + 3) * 68 + j] = t0.w;
            Ks[(d0 + 4) * 68 + j] = t1.x; Ks[(d0 + 5) * 68 + j] = t1.y;
            Ks[(d0 + 6) * 68 + j] = t1.z; Ks[(d0 + 7) * 68 + j] = t1.w;
        }
        __syncthreads();

        float acc[4][2] = {};
        #pragma unroll 4
        for (int d = 0; d < 64; d++) {
            float w = vps[d];
            float4 qv = *(const float4*)&Qs[d * 68 + ti * 4];
            float2 kv = *(const float2*)&Ks[d * 68 + tj * 2];
            float qa[4] = {qv.x, qv.y, qv.z, qv.w};
            float kb[2] = {kv.x, kv.y};
            #pragma unroll
            for (int a = 0; a < 4; a++)
                #pragma unroll
                for (int c = 0; c < 2; c++)
                    acc[a][c] += w * tanh_fast(qa[a] + kb[c]);
        }
        #pragma unroll
        for (int a = 0; a < 4; a++)
            #pragma unroll
            for (int c = 0; c < 2; c++)
                S[(ti * 4 + a) * 260 + jb * 64 + tj * 2 + c] = acc[a][c];
    }
    __syncthreads();

    {
        int warp = tid >> 5, lane = tid & 31;
        #pragma unroll
        for (int r = 0; r < 4; r++) {
            int row = warp * 4 + r;
            const int* mrow = mask + ((size_t)b * L_ + i0 + row) * L_;
            float vals[8];
            float mmax = -3.4e38f;
            #pragma unroll
            for (int c8 = 0; c8 < 8; c8++) {
                int c = c8 * 32 + lane;
                float s = S[row * 260 + c];
                if (mrow[c] == 0) s = -1.0e9f;
                vals[c8] = s;
                mmax = fmaxf(mmax, s);
            }
            #pragma unroll
            for (int off = 16; off > 0; off >>= 1)
                mmax = fmaxf(mmax, __shfl_xor_sync(0xFFFFFFFFu, mmax, off));
            float sum = 0.0f;
            #pragma unroll
            for (int c8 = 0; c8 < 8; c8++) {
                float e = __expf(vals[c8] - mmax);
                S[row * 260 + c8 * 32 + lane] = e;
                sum += e;
            }
            #pragma unroll
            for (int off = 16; off > 0; off >>= 1)
                sum += __shfl_xor_sync(0xFFFFFFFFu, sum, off);
            if (lane == 0) rinv[row] = 1.0f / sum;
        }
    }
    __syncthreads();

    {
        int i   = tid >> 3;
        int dk0 = (tid & 7) * 8;
        float o[8] = {};
        #pragma unroll 4
        for (int j = 0; j < L_; j++) {
            float p = S[i * 260 + j];
            float4 v0 = *(const float4*)&Vs[j * DK_ + dk0];
            float4 v1 = *(const float4*)&Vs[j * DK_ + dk0 + 4];
            o[0] += p * v0.x; o[1] += p * v0.y; o[2] += p * v0.z; o[3] += p * v0.w;
            o[4] += p * v1.x; o[5] += p * v1.y; o[6] += p * v1.z; o[7] += p * v1.w;
        }
        float inv = rinv[i];
        size_t off = ((size_t)(b * L_ + i0 + i)) * D_ + h * DK_ + dk0;
        bf162* ph = (bf162*)&g_ctx_hi[off];
        bf162* pl = (bf162*)&g_ctx_lo[off];
        #pragma unroll
        for (int u = 0; u < 4; u++) {
            float va = o[u * 2] * inv, vb = o[u * 2 + 1] * inv;
            bf16 ha, la, hb, lb;
            split_bf(va, ha, la);
            split_bf(vb, hb, lb);
            ph[u] = bf162(ha, hb);
            pl[u] = bf162(la, lb);
        }
    }
}

// ===========================================================================
extern "C" void kernel_launch(void* const* d_in, const int* in_sizes, int n_in,
                              void* d_out, int out_size)
{
    const float* q    = (const float*)d_in[0];
    const float* k    = (const float*)d_in[1];
    const float* v    = (const float*)d_in[2];
    const int*   mask = (const int*)  d_in[3];
    const float* Wq   = (const float*)d_in[4];
    const float* bq   = (const float*)d_in[5];
    const float* Wk   = (const float*)d_in[6];
    const float* bk   = (const float*)d_in[7];
    const float* Wv   = (const float*)d_in[8];
    const float* bv   = (const float*)d_in[9];
    const float* vp   = (const float*)d_in[10];
    const float* W0   = (const float*)d_in[11];
    const float* b0   = (const float*)d_in[12];
    float* out = (float*)d_out;

    static bool attr_set = false;
    if (!attr_set) {
        cudaFuncSetAttribute(attn_kernel,
                             cudaFuncAttributeMaxDynamicSharedMemorySize, ATTN_SMEM_BYTES);
        cudaFuncSetAttribute(qkv_mma_kernel,
                             cudaFuncAttributeMaxDynamicSharedMemorySize, GEMM_SMEM_BYTES);
        cudaFuncSetAttribute(out_mma_kernel,
                             cudaFuncAttributeMaxDynamicSharedMemorySize, GEMM_SMEM_BYTES);
        attr_set = true;
    }

    convert_x_kernel<<<dim3(512, 3), 256>>>(q, k, v);
    convert_w_kernel<<<dim3(16, 16, 4), dim3(32, 8)>>>(Wq, Wk, Wv, W0);
    qkv_mma_kernel<<<dim3(8, 8, 3), 256, GEMM_SMEM_BYTES>>>(bq, bk, bv);
    attn_kernel<<<dim3(4, 32), 512, ATTN_SMEM_BYTES>>>(mask, vp);
    out_mma_kernel<<<dim3(8, 8), 256, GEMM_SMEM_BYTES>>>(b0, out);
}